// round 16
// baseline (speedup 1.0000x reference)
#include <cuda_runtime.h>
#include <stdint.h>
#include <math.h>

// HermanModel spiking network — bit-faithful replication of the JAX/XLA-CPU
// reference (partitionable Threefry, XLA ErfInv, eid-ordered scatter chain).
// Persistent step kernel (290 blocks co-resident, 2/SM) with a software grid
// barrier carrying full release/ACQUIRE semantics. Act traffic via L2
// (ld.global.cg / st.global.cg); L2 is the coherence point.

#define NN      100000
#define EE      6400000
#define MAXDEG  192
#define NSTEPS  100

#define NPB     345            // neurons per step-block
#define TPB     512            // threads per block
#define NB      290            // ceil(100000/345) = 290 <= 296 resident capacity
#define CAP     24576          // staged slots per block (96KB smem); < 2^15
#define NBUCK   1563           // src buckets of 64

struct __align__(8)  GEnt  { unsigned packed; float w; };    // (src<<15)|pos

// ---- static scratch (no allocs allowed) ----
__device__ int      g_is64;
__device__ unsigned g_thr;                        // filt bit-threshold; ~0u = fallback
__device__ unsigned g_barcnt;                     // grid-barrier arrival counter
__device__ int      g_cnt[NN];
__device__ int      g_deg[NN];
__device__ uint4    g_tmpE[(size_t)MAXDEG * NN];  // {src, w_bits, eid, 0} [i*192+s]
__device__ unsigned g_lofs[NN];                   // block-local padded CSR offset
__device__ int      g_m[NB];                      // padded slot count per block
__device__ int      g_medge[NB];                  // real edge count per block
__device__ unsigned g_bcnt[(size_t)NB * NBUCK];   // bucket counts per step-block
__device__ GEnt     g_g[(size_t)NB * CAP];        // src-clustered gather list
__device__ float    g_actA[NN];
__device__ float    g_actB[NN];
__device__ float    g_spk[(size_t)NSTEPS * NN];   // [t][i]

// ---------------- Threefry-2x32 (JAX's 20-round cipher) ----------------
__host__ __device__ __forceinline__ unsigned rotl32(unsigned x, int r) {
    return (x << r) | (x >> (32 - r));
}
__host__ __device__ __forceinline__ void tf2x32(unsigned k0, unsigned k1,
                                                unsigned x0, unsigned x1,
                                                unsigned &o0, unsigned &o1)
{
    unsigned k2 = k0 ^ k1 ^ 0x1BD11BDAu;
    x0 += k0; x1 += k1;
#define TF_R(r) { x0 += x1; x1 = rotl32(x1, r); x1 ^= x0; }
#define TF_G1   TF_R(13) TF_R(15) TF_R(26) TF_R(6)
#define TF_G2   TF_R(17) TF_R(29) TF_R(16) TF_R(24)
    TF_G1  x0 += k1; x1 += k2 + 1u;
    TF_G2  x0 += k2; x1 += k0 + 2u;
    TF_G1  x0 += k0; x1 += k1 + 3u;
    TF_G2  x0 += k1; x1 += k2 + 4u;
    TF_G1  x0 += k2; x1 += k0 + 5u;
#undef TF_G1
#undef TF_G2
#undef TF_R
    o0 = x0; o1 = x1;
}

// ---------------- XLA math replication (strict f32, no FMA) ----------------
__device__ __forceinline__ float xla_log1p(float v) {
    if (fabsf(v) < 1e-4f)
        return __fmul_rn(__fadd_rn(__fmul_rn(-0.5f, v), 1.0f), v);
    return (float)log((double)__fadd_rn(v, 1.0f));
}
__device__ __forceinline__ float xla_erfinv(float x) {
    float w = -xla_log1p(-__fmul_rn(x, x));
    float p;
    if (w < 5.0f) {
        w = __fadd_rn(w, -2.5f);
        p =  2.81022636e-08f;
        p = __fadd_rn( 3.43273939e-07f, __fmul_rn(p, w));
        p = __fadd_rn(-3.5233877e-06f,  __fmul_rn(p, w));
        p = __fadd_rn(-4.39150654e-06f, __fmul_rn(p, w));
        p = __fadd_rn( 0.00021858087f,  __fmul_rn(p, w));
        p = __fadd_rn(-0.00125372503f,  __fmul_rn(p, w));
        p = __fadd_rn(-0.00417768164f,  __fmul_rn(p, w));
        p = __fadd_rn( 0.246640727f,    __fmul_rn(p, w));
        p = __fadd_rn( 1.50140941f,     __fmul_rn(p, w));
    } else {
        w = __fadd_rn(sqrtf(w), -3.0f);
        p = -0.000200214257f;
        p = __fadd_rn( 0.000100950558f, __fmul_rn(p, w));
        p = __fadd_rn( 0.00134934322f,  __fmul_rn(p, w));
        p = __fadd_rn(-0.00367342844f,  __fmul_rn(p, w));
        p = __fadd_rn( 0.00573950773f,  __fmul_rn(p, w));
        p = __fadd_rn(-0.0076224613f,   __fmul_rn(p, w));
        p = __fadd_rn( 0.00943887047f,  __fmul_rn(p, w));
        p = __fadd_rn( 1.00167406f,     __fmul_rn(p, w));
        p = __fadd_rn( 2.83297682f,     __fmul_rn(p, w));
    }
    return __fmul_rn(p, x);
}
__device__ __forceinline__ float bits_to_normal(unsigned bits) {
    const float LO = -0.99999994f;
    float f = __fadd_rn(__uint_as_float((bits >> 9) | 0x3F800000u), -1.0f);
    float u = __fadd_rn(__fmul_rn(f, 2.0f), LO);
    u = fmaxf(LO, u);
    return __fmul_rn(1.41421356f, xla_erfinv(u));
}

// L2-coherent accesses (L2 = coherence point across the software barrier)
__device__ __forceinline__ float ldcg_f32(const float* p) {
    float v;
    asm volatile("ld.global.cg.f32 %0, [%1];" : "=f"(v) : "l"(p));
    return v;
}
__device__ __forceinline__ void stcg_f32(float* p, float v) {
    asm volatile("st.global.cg.f32 [%0], %1;" :: "l"(p), "f"(v) : "memory");
}

// ---------------- launch 0: zero + init (dtype detect, filt threshold) ----
__global__ void prep_zero(const void* ei) {
    size_t i = (size_t)blockIdx.x * blockDim.x + threadIdx.x;
    if (i < NN) g_cnt[i] = 0;
    if (i < (size_t)NB * NBUCK) g_bcnt[i] = 0;

    if (blockIdx.x == 0 && threadIdx.x == 0) {
        g_barcnt = 0u;                       // reset per graph replay
        const unsigned long long* p = (const unsigned long long*)ei;
        int ok64 = 1;
        for (int k = 0; k < 64; ++k)
            if (p[k] >= (unsigned long long)NN) { ok64 = 0; break; }
        g_is64 = ok64;

        unsigned lo = 0, hi = 1u << 23;
        while (lo < hi) {
            unsigned mid = (lo + hi) >> 1;
            if (bits_to_normal(mid << 9) > 1.5f) hi = mid; else lo = mid + 1;
        }
        unsigned thr = lo, bad = 0;
        unsigned a = (thr > 512u) ? thr - 512u : 0u;
        unsigned b = (thr + 512u < (1u << 23)) ? thr + 512u : (1u << 23);
        for (unsigned m = a; m < b; ++m) {
            bool big = bits_to_normal(m << 9) > 1.5f;
            if (big != (m >= thr)) { bad = 1; break; }
        }
        g_thr = bad ? 0xFFFFFFFFu : thr;
    }
}

// ---------------- launch 1: bin edges (16B record) + bucket counts --------
__global__ void prep_scatter(const void* __restrict__ ei,
                             const float* __restrict__ W)
{
    int e = blockIdx.x * blockDim.x + threadIdx.x;
    if (e >= EE) return;
    int s, d;
    if (g_is64) {
        const long long* p = (const long long*)ei;
        s = (int)p[e]; d = (int)p[(size_t)EE + e];
    } else {
        const int* p = (const int*)ei;
        s = p[e]; d = p[EE + e];
    }
    if ((unsigned)s >= NN || (unsigned)d >= NN) return;
    int slot = atomicAdd(&g_cnt[d], 1);
    if (slot < MAXDEG) {
        g_tmpE[(size_t)d * MAXDEG + slot] =
            make_uint4((unsigned)s, __float_as_uint(W[e]), (unsigned)e, 0u);
        int blk = d / NPB;
        atomicAdd(&g_bcnt[(size_t)blk * NBUCK + ((unsigned)s >> 6)], 1u);
    }
}

// ---------------- launch 2: per-block scan of (deg+1) -> padded CSR -------
__global__ void __launch_bounds__(TPB) prep_csr(const float* __restrict__ act0)
{
    __shared__ unsigned sa[TPB], sb[TPB];
    int blk = blockIdx.x, tid = threadIdx.x;
    int i = blk * NPB + tid;
    unsigned dd = 0u;
    if (tid < NPB && i < NN) {
        int c = g_cnt[i]; if (c > MAXDEG) c = MAXDEG;
        g_deg[i] = c;
        g_actA[i] = act0[i];
        dd = (unsigned)(c + 1);
    }
    sa[tid] = dd;
    __syncthreads();
    unsigned *in = sa, *out = sb;
    for (int off = 1; off < TPB; off <<= 1) {
        out[tid] = in[tid] + ((tid >= off) ? in[tid - off] : 0u);
        __syncthreads();
        unsigned* t = in; in = out; out = t;
    }
    unsigned incl = in[tid];
    if (tid < NPB && i < NN) g_lofs[i] = incl - dd;
    if (tid == TPB - 1) g_m[blk] = (int)incl;
}

// ---------------- warp ranking, templated on chain count ----------------
template <int NCH>
__device__ __forceinline__ void rank_and_emit(
    const uint4* te, int d, unsigned lo,
    unsigned* cur, GEnt* gl, int lane)
{
    unsigned key[NCH], srcv[NCH], wbits[NCH];
    #pragma unroll
    for (int c = 0; c < NCH; ++c) {
        int s = c * 32 + lane;
        if (s < d) {
            uint4 u4 = te[s];
            srcv[c] = u4.x; wbits[c] = u4.y; key[c] = u4.z;
        } else {
            key[c] = 0xFFFFFFFFu; srcv[c] = 0u; wbits[c] = 0u;
        }
    }
    int rank[NCH];
    #pragma unroll
    for (int c = 0; c < NCH; ++c) rank[c] = 0;
    #pragma unroll
    for (int c2 = 0; c2 < NCH; ++c2) {
        unsigned kc = key[c2];
        #pragma unroll
        for (int l = 0; l < 32; ++l) {
            unsigned kj = __shfl_sync(0xFFFFFFFFu, kc, l);
            if (kj != 0xFFFFFFFFu) {
                #pragma unroll
                for (int c = 0; c < NCH; ++c)
                    rank[c] += (kj < key[c]) ? 1 : 0;
            }
        }
    }
    #pragma unroll
    for (int c = 0; c < NCH; ++c) {
        int s = c * 32 + lane;
        if (s < d) {
            unsigned pos = lo + (unsigned)rank[c];
            unsigned idx = atomicAdd(&cur[srcv[c] >> 6], 1u);
            if (idx < CAP && pos < CAP) {
                GEnt g; g.packed = (srcv[c] << 15) | pos;
                g.w = __uint_as_float(wbits[c]);
                gl[idx] = g;
            }
        }
    }
}

// ---------------- launch 3: fused bucket-scan + rank + fill ----------------
__global__ void __launch_bounds__(1024) prep_rankfill()
{
    __shared__ unsigned cur[NBUCK];
    __shared__ unsigned part[1024], pa[1024], pb[1024];
    int blk = blockIdx.x, tid = threadIdx.x;
    int wid = tid >> 5, lane = tid & 31;
    unsigned* c = &g_bcnt[(size_t)blk * NBUCK];

    const int PER = (NBUCK + 1023) / 1024;   // 2
    unsigned s0 = 0;
    for (int k = 0; k < PER; ++k) {
        int idx = tid * PER + k;
        if (idx < NBUCK) s0 += c[idx];
    }
    part[tid] = s0; pa[tid] = s0;
    __syncthreads();
    unsigned *in = pa, *out = pb;
    for (int off = 1; off < 1024; off <<= 1) {
        out[tid] = in[tid] + ((tid >= off) ? in[tid - off] : 0u);
        __syncthreads();
        unsigned* t = in; in = out; out = t;
    }
    if (tid == 1023) g_medge[blk] = (int)in[1023];
    unsigned base = in[tid] - part[tid];
    for (int k = 0; k < PER; ++k) {
        int idx = tid * PER + k;
        if (idx < NBUCK) { cur[idx] = base; base += c[idx]; }
    }
    __syncthreads();

    GEnt* gl = &g_g[(size_t)blk * CAP];
    const int NIT = (NPB + 31) / 32;         // 11
    for (int it = 0; it < NIT; ++it) {
        int li = it * 32 + wid;
        int i = blk * NPB + li;
        if (li >= NPB || i >= NN) continue;
        int d = g_deg[i];
        unsigned lo = g_lofs[i];
        const uint4* te = &g_tmpE[(size_t)i * MAXDEG];
        if (d <= 64)       rank_and_emit<2>(te, d, lo, cur, gl, lane);
        else if (d <= 96)  rank_and_emit<3>(te, d, lo, cur, gl, lane);
        else               rank_and_emit<6>(te, d, lo, cur, gl, lane);
    }
}

// ---------------- launch 4: persistent kernel, all 100 steps ----------------
__global__ void __launch_bounds__(TPB, 2) step_all()
{
    extern __shared__ float sval[];          // CAP floats = 96KB
    int blk = blockIdx.x;
    int li = threadIdx.x;
    int i = blk * NPB + li;
    bool alive = (li < NPB && i < NN);

    // per-thread invariants, loaded once for all 100 steps
    int mpad = g_m[blk];
    int me   = g_medge[blk];
    bool staged = (mpad <= CAP && me <= CAP);
    int      d  = alive ? g_deg[i] : 0;
    unsigned lo = alive ? g_lofs[i] : 0u;
    const GEnt* gl = &g_g[(size_t)blk * CAP];
    unsigned thr = g_thr;

    for (int t = 0; t < NSTEPS; ++t) {
        const float* actIn  = (t & 1) ? g_actB : g_actA;
        float*       actOut = (t & 1) ? g_actA : g_actB;

        // per-step keys (redundant per thread; pure ALU, overlaps memory)
        unsigned kt0, kt1, n0, n1, f0, f1;
        tf2x32(0u, 42u, 0u, (unsigned)t, kt0, kt1);
        tf2x32(kt0, kt1, 0u, 0u, n0, n1);
        tf2x32(kt0, kt1, 0u, 1u, f0, f1);

        // PRNG hoisted above gather (overlaps the LTS-bound phase)
        float bterm = 0.001f;
        if (alive) {
            unsigned b0, b1;
            tf2x32(f0, f1, 0u, (unsigned)i, b0, b1);
            unsigned fb = b0 ^ b1;
            bool filt = (thr != 0xFFFFFFFFu) ? ((fb >> 9) >= thr)
                                             : (bits_to_normal(fb) > 1.5f);
            if (filt) {
                tf2x32(n0, n1, 0u, (unsigned)i, b0, b1);
                float noise = __fmul_rn(0.3f, bits_to_normal(b0 ^ b1));
                bterm = __fmul_rn(0.001f, __fadd_rn(1.0f, noise));
            }
        }

        if (staged) {
            for (int j = li; j < me; j += TPB) {
                uint2 gr = __ldg((const uint2*)&gl[j]);      // 8B static-list load
                unsigned packed = gr.x;
                float    wv     = __uint_as_float(gr.y);
                sval[packed & 0x7FFFu] =
                    __fmul_rn(wv, ldcg_f32(&actIn[packed >> 15]));
            }
        }
        __syncthreads();

        if (alive) {
            float acc = 0.0f;
            if (staged) {
                #pragma unroll 8
                for (int s = 0; s < d; ++s)
                    acc = __fadd_rn(acc, sval[lo + s]);      // eid-ordered chain
            } else {
                // never-taken safety net: selection by min eid over raw records
                const uint4* te = &g_tmpE[(size_t)i * MAXDEG];
                unsigned done[6] = {0, 0, 0, 0, 0, 0};
                for (int r = 0; r < d; ++r) {
                    unsigned bestk = 0xFFFFFFFFu; int bs = 0;
                    unsigned bsrc = 0, bw = 0;
                    for (int s = 0; s < d; ++s) {
                        if (done[s >> 5] & (1u << (s & 31))) continue;
                        uint4 u4 = te[s];
                        if (u4.z < bestk) { bestk = u4.z; bs = s; bsrc = u4.x; bw = u4.y; }
                    }
                    done[bs >> 5] |= 1u << (bs & 31);
                    acc = __fadd_rn(acc,
                        __fmul_rn(__uint_as_float(bw), ldcg_f32(&actIn[bsrc])));
                }
            }

            float l = __fadd_rn(__fmul_rn(0.025f, acc), bterm);
            float spike = (l > 0.001378f) ? 1.0f : 0.0f;
            float na = __fsub_rn(__fadd_rn(acc, spike),
                                 __fmul_rn(__fdiv_rn(acc, 0.01f), 1e-4f));
            g_spk[(size_t)t * NN + i] = spike;
            stcg_f32(&actOut[i], na);        // L2 write-through (coherence point)
        }

        // software grid barrier with full release/ACQUIRE semantics
        if (t < NSTEPS - 1) {
            __threadfence();                 // release: stores -> L2, all threads
            __syncthreads();
            if (threadIdx.x == 0) {
                atomicAdd(&g_barcnt, 1u);
                unsigned target = (unsigned)NB * (unsigned)(t + 1);
                unsigned v;
                do {
                    asm volatile("ld.acquire.gpu.global.u32 %0, [%1];"
                                 : "=r"(v) : "l"(&g_barcnt) : "memory");
                } while (v < target);
                __threadfence();             // acquire side: order post-barrier ops
            }
            __syncthreads();
        }
    }
}

// ---------------- last launch: [t][i] -> [i][t] transpose ----------------
__global__ void trans_k(float* __restrict__ out)
{
    __shared__ float tile[32][33];
    int i0 = blockIdx.x * 32, t0 = blockIdx.y * 32;
    int tr = t0 + threadIdx.y, ic = i0 + threadIdx.x;
    tile[threadIdx.y][threadIdx.x] =
        (tr < NSTEPS && ic < NN) ? g_spk[(size_t)tr * NN + ic] : 0.0f;
    __syncthreads();
    int iw = i0 + threadIdx.y, tw = t0 + threadIdx.x;
    if (iw < NN && tw < NSTEPS)
        out[(size_t)iw * NSTEPS + tw] = tile[threadIdx.x][threadIdx.y];
}

// ---------------- host ----------------
extern "C" void kernel_launch(void* const* d_in, const int* in_sizes, int n_in,
                              void* d_out, int out_size)
{
    const float* act0 = (const float*)d_in[0];
    const float* W    = (const float*)d_in[1];
    const void*  ei   = d_in[2];
    float*       out  = (float*)d_out;

    cudaFuncSetAttribute(step_all, cudaFuncAttributeMaxDynamicSharedMemorySize,
                         CAP * (int)sizeof(float));

    {
        size_t zn = (size_t)NB * NBUCK;
        prep_zero<<<(int)((zn + 255) / 256), 256>>>(ei);           // launch 0
    }
    prep_scatter <<<(EE + 255) / 256, 256>>>(ei, W);               // launch 1
    prep_csr     <<<NB, TPB>>>(act0);                              // launch 2
    prep_rankfill<<<NB, 1024>>>();                                 // launch 3

    step_all<<<NB, TPB, CAP * sizeof(float)>>>();                  // launch 4

    trans_k<<<dim3((NN + 31) / 32, (NSTEPS + 31) / 32), dim3(32, 32)>>>(out);
}

// round 17
// speedup vs baseline: 1.0783x; 1.0783x over previous
#include <cuda_runtime.h>
#include <stdint.h>
#include <math.h>

// HermanModel spiking network — bit-faithful replication of the JAX/XLA-CPU
// reference (partitionable Threefry, XLA ErfInv, eid-ordered scatter chain).
// Round-11 multi-launch architecture (proven 2219us) with step_k widened to
// 1024 threads/block (64 warps/SM in the latency-bound gather phase).

#define NN      100000
#define EE      6400000
#define MAXDEG  192
#define NSTEPS  100

#define NPB     340            // neurons per step-block
#define TPB     512            // prep_csr threads (scan width)
#define STPB    1024           // step_k threads per block
#define NB      295            // ceil(NN/NPB)
#define CAP     24576          // staged slots per block (96KB); < 2^15
#define NBUCK   1563           // src buckets of 64

struct __align__(8)  GEnt  { unsigned packed; float w; };    // (src<<15)|pos

// ---- static scratch (no allocs allowed) ----
__device__ int      g_is64;
__device__ unsigned g_thr;                        // filt bit-threshold; ~0u = fallback
__device__ int      g_cnt[NN];
__device__ int      g_deg[NN];
__device__ uint4    g_tmpE[(size_t)MAXDEG * NN];  // {src, w_bits, eid, 0} [i*192+s]
__device__ unsigned g_lofs[NN];                   // block-local padded CSR offset
__device__ int      g_m[NB];                      // padded slot count per block
__device__ int      g_medge[NB];                  // real edge count per block
__device__ unsigned g_bcnt[(size_t)NB * NBUCK];   // bucket counts per step-block
__device__ GEnt     g_g[(size_t)NB * CAP];        // src-clustered gather list
__device__ float    g_actA[NN];
__device__ float    g_actB[NN];
__device__ float    g_spk[(size_t)NSTEPS * NN];   // [t][i]

// ---------------- Threefry-2x32 (JAX's 20-round cipher) ----------------
__host__ __device__ __forceinline__ unsigned rotl32(unsigned x, int r) {
    return (x << r) | (x >> (32 - r));
}
__host__ __device__ __forceinline__ void tf2x32(unsigned k0, unsigned k1,
                                                unsigned x0, unsigned x1,
                                                unsigned &o0, unsigned &o1)
{
    unsigned k2 = k0 ^ k1 ^ 0x1BD11BDAu;
    x0 += k0; x1 += k1;
#define TF_R(r) { x0 += x1; x1 = rotl32(x1, r); x1 ^= x0; }
#define TF_G1   TF_R(13) TF_R(15) TF_R(26) TF_R(6)
#define TF_G2   TF_R(17) TF_R(29) TF_R(16) TF_R(24)
    TF_G1  x0 += k1; x1 += k2 + 1u;
    TF_G2  x0 += k2; x1 += k0 + 2u;
    TF_G1  x0 += k0; x1 += k1 + 3u;
    TF_G2  x0 += k1; x1 += k2 + 4u;
    TF_G1  x0 += k2; x1 += k0 + 5u;
#undef TF_G1
#undef TF_G2
#undef TF_R
    o0 = x0; o1 = x1;
}

// ---------------- XLA math replication (strict f32, no FMA) ----------------
__device__ __forceinline__ float xla_log1p(float v) {
    if (fabsf(v) < 1e-4f)
        return __fmul_rn(__fadd_rn(__fmul_rn(-0.5f, v), 1.0f), v);
    return (float)log((double)__fadd_rn(v, 1.0f));
}
__device__ __forceinline__ float xla_erfinv(float x) {
    float w = -xla_log1p(-__fmul_rn(x, x));
    float p;
    if (w < 5.0f) {
        w = __fadd_rn(w, -2.5f);
        p =  2.81022636e-08f;
        p = __fadd_rn( 3.43273939e-07f, __fmul_rn(p, w));
        p = __fadd_rn(-3.5233877e-06f,  __fmul_rn(p, w));
        p = __fadd_rn(-4.39150654e-06f, __fmul_rn(p, w));
        p = __fadd_rn( 0.00021858087f,  __fmul_rn(p, w));
        p = __fadd_rn(-0.00125372503f,  __fmul_rn(p, w));
        p = __fadd_rn(-0.00417768164f,  __fmul_rn(p, w));
        p = __fadd_rn( 0.246640727f,    __fmul_rn(p, w));
        p = __fadd_rn( 1.50140941f,     __fmul_rn(p, w));
    } else {
        w = __fadd_rn(sqrtf(w), -3.0f);
        p = -0.000200214257f;
        p = __fadd_rn( 0.000100950558f, __fmul_rn(p, w));
        p = __fadd_rn( 0.00134934322f,  __fmul_rn(p, w));
        p = __fadd_rn(-0.00367342844f,  __fmul_rn(p, w));
        p = __fadd_rn( 0.00573950773f,  __fmul_rn(p, w));
        p = __fadd_rn(-0.0076224613f,   __fmul_rn(p, w));
        p = __fadd_rn( 0.00943887047f,  __fmul_rn(p, w));
        p = __fadd_rn( 1.00167406f,     __fmul_rn(p, w));
        p = __fadd_rn( 2.83297682f,     __fmul_rn(p, w));
    }
    return __fmul_rn(p, x);
}
__device__ __forceinline__ float bits_to_normal(unsigned bits) {
    const float LO = -0.99999994f;
    float f = __fadd_rn(__uint_as_float((bits >> 9) | 0x3F800000u), -1.0f);
    float u = __fadd_rn(__fmul_rn(f, 2.0f), LO);
    u = fmaxf(LO, u);
    return __fmul_rn(1.41421356f, xla_erfinv(u));
}

// ---------------- launch 0: zero + init (dtype detect, filt threshold) ----
__global__ void prep_zero(const void* ei) {
    size_t i = (size_t)blockIdx.x * blockDim.x + threadIdx.x;
    if (i < NN) g_cnt[i] = 0;
    if (i < (size_t)NB * NBUCK) g_bcnt[i] = 0;

    if (blockIdx.x == 0 && threadIdx.x == 0) {
        const unsigned long long* p = (const unsigned long long*)ei;
        int ok64 = 1;
        for (int k = 0; k < 64; ++k)
            if (p[k] >= (unsigned long long)NN) { ok64 = 0; break; }
        g_is64 = ok64;

        unsigned lo = 0, hi = 1u << 23;
        while (lo < hi) {
            unsigned mid = (lo + hi) >> 1;
            if (bits_to_normal(mid << 9) > 1.5f) hi = mid; else lo = mid + 1;
        }
        unsigned thr = lo, bad = 0;
        unsigned a = (thr > 512u) ? thr - 512u : 0u;
        unsigned b = (thr + 512u < (1u << 23)) ? thr + 512u : (1u << 23);
        for (unsigned m = a; m < b; ++m) {
            bool big = bits_to_normal(m << 9) > 1.5f;
            if (big != (m >= thr)) { bad = 1; break; }
        }
        g_thr = bad ? 0xFFFFFFFFu : thr;
    }
}

// ---------------- launch 1: bin edges (16B record) + bucket counts --------
__global__ void prep_scatter(const void* __restrict__ ei,
                             const float* __restrict__ W)
{
    int e = blockIdx.x * blockDim.x + threadIdx.x;
    if (e >= EE) return;
    int s, d;
    if (g_is64) {
        const long long* p = (const long long*)ei;
        s = (int)p[e]; d = (int)p[(size_t)EE + e];
    } else {
        const int* p = (const int*)ei;
        s = p[e]; d = p[EE + e];
    }
    if ((unsigned)s >= NN || (unsigned)d >= NN) return;
    int slot = atomicAdd(&g_cnt[d], 1);
    if (slot < MAXDEG) {
        g_tmpE[(size_t)d * MAXDEG + slot] =
            make_uint4((unsigned)s, __float_as_uint(W[e]), (unsigned)e, 0u);
        int blk = d / NPB;
        atomicAdd(&g_bcnt[(size_t)blk * NBUCK + ((unsigned)s >> 6)], 1u);
    }
}

// ---------------- launch 2: per-block scan of (deg+1) -> padded CSR -------
__global__ void __launch_bounds__(TPB) prep_csr(const float* __restrict__ act0)
{
    __shared__ unsigned sa[TPB], sb[TPB];
    int blk = blockIdx.x, tid = threadIdx.x;
    int i = blk * NPB + tid;
    unsigned dd = 0u;
    if (tid < NPB && i < NN) {
        int c = g_cnt[i]; if (c > MAXDEG) c = MAXDEG;
        g_deg[i] = c;
        g_actA[i] = act0[i];
        dd = (unsigned)(c + 1);
    }
    sa[tid] = dd;
    __syncthreads();
    unsigned *in = sa, *out = sb;
    for (int off = 1; off < TPB; off <<= 1) {
        out[tid] = in[tid] + ((tid >= off) ? in[tid - off] : 0u);
        __syncthreads();
        unsigned* t = in; in = out; out = t;
    }
    unsigned incl = in[tid];
    if (tid < NPB && i < NN) g_lofs[i] = incl - dd;
    if (tid == TPB - 1) g_m[blk] = (int)incl;
}

// ---------------- warp ranking, templated on chain count ----------------
template <int NCH>
__device__ __forceinline__ void rank_and_emit(
    const uint4* te, int d, unsigned lo,
    unsigned* cur, GEnt* gl, int lane)
{
    unsigned key[NCH], srcv[NCH], wbits[NCH];
    #pragma unroll
    for (int c = 0; c < NCH; ++c) {
        int s = c * 32 + lane;
        if (s < d) {
            uint4 u4 = te[s];
            srcv[c] = u4.x; wbits[c] = u4.y; key[c] = u4.z;
        } else {
            key[c] = 0xFFFFFFFFu; srcv[c] = 0u; wbits[c] = 0u;
        }
    }
    int rank[NCH];
    #pragma unroll
    for (int c = 0; c < NCH; ++c) rank[c] = 0;
    #pragma unroll
    for (int c2 = 0; c2 < NCH; ++c2) {
        unsigned kc = key[c2];
        #pragma unroll
        for (int l = 0; l < 32; ++l) {
            unsigned kj = __shfl_sync(0xFFFFFFFFu, kc, l);
            if (kj != 0xFFFFFFFFu) {
                #pragma unroll
                for (int c = 0; c < NCH; ++c)
                    rank[c] += (kj < key[c]) ? 1 : 0;
            }
        }
    }
    #pragma unroll
    for (int c = 0; c < NCH; ++c) {
        int s = c * 32 + lane;
        if (s < d) {
            unsigned pos = lo + (unsigned)rank[c];
            unsigned idx = atomicAdd(&cur[srcv[c] >> 6], 1u);
            if (idx < CAP && pos < CAP) {
                GEnt g; g.packed = (srcv[c] << 15) | pos;
                g.w = __uint_as_float(wbits[c]);
                gl[idx] = g;
            }
        }
    }
}

// ---------------- launch 3: fused bucket-scan + rank + fill ----------------
__global__ void __launch_bounds__(1024) prep_rankfill()
{
    __shared__ unsigned cur[NBUCK];
    __shared__ unsigned part[1024], pa[1024], pb[1024];
    int blk = blockIdx.x, tid = threadIdx.x;
    int wid = tid >> 5, lane = tid & 31;
    unsigned* c = &g_bcnt[(size_t)blk * NBUCK];

    const int PER = (NBUCK + 1023) / 1024;   // 2
    unsigned s0 = 0;
    for (int k = 0; k < PER; ++k) {
        int idx = tid * PER + k;
        if (idx < NBUCK) s0 += c[idx];
    }
    part[tid] = s0; pa[tid] = s0;
    __syncthreads();
    unsigned *in = pa, *out = pb;
    for (int off = 1; off < 1024; off <<= 1) {
        out[tid] = in[tid] + ((tid >= off) ? in[tid - off] : 0u);
        __syncthreads();
        unsigned* t = in; in = out; out = t;
    }
    if (tid == 1023) g_medge[blk] = (int)in[1023];
    unsigned base = in[tid] - part[tid];
    for (int k = 0; k < PER; ++k) {
        int idx = tid * PER + k;
        if (idx < NBUCK) { cur[idx] = base; base += c[idx]; }
    }
    __syncthreads();

    GEnt* gl = &g_g[(size_t)blk * CAP];
    const int NIT = (NPB + 31) / 32;         // 11
    for (int it = 0; it < NIT; ++it) {
        int li = it * 32 + wid;
        int i = blk * NPB + li;
        if (li >= NPB || i >= NN) continue;
        int d = g_deg[i];
        unsigned lo = g_lofs[i];
        const uint4* te = &g_tmpE[(size_t)i * MAXDEG];
        if (d <= 64)       rank_and_emit<2>(te, d, lo, cur, gl, lane);
        else if (d <= 96)  rank_and_emit<3>(te, d, lo, cur, gl, lane);
        else               rank_and_emit<6>(te, d, lo, cur, gl, lane);
    }
}

// ---------------- launches 4..103: fused simulation step ----------------
__global__ void __launch_bounds__(STPB, 2) step_k(
    int t, int parity,
    unsigned kn0, unsigned kn1, unsigned kf0, unsigned kf1)
{
    extern __shared__ float sval[];          // CAP floats = 96KB
    int blk = blockIdx.x;
    const float* actIn  = parity ? g_actB : g_actA;
    float*       actOut = parity ? g_actA : g_actB;
    int mpad = g_m[blk];
    int me   = g_medge[blk];
    bool staged = (mpad <= CAP && me <= CAP);

    int li = threadIdx.x;
    int i = blk * NPB + li;
    bool alive = (li < NPB && i < NN);

    // PRNG hoisted: depends only on i; overlaps the LTS-bound gather
    float bterm = 0.001f;
    if (alive) {
        unsigned b0, b1;
        tf2x32(kf0, kf1, 0u, (unsigned)i, b0, b1);
        unsigned fb = b0 ^ b1;
        unsigned thr = g_thr;
        bool filt = (thr != 0xFFFFFFFFu) ? ((fb >> 9) >= thr)
                                         : (bits_to_normal(fb) > 1.5f);
        if (filt) {
            tf2x32(kn0, kn1, 0u, (unsigned)i, b0, b1);
            float noise = __fmul_rn(0.3f, bits_to_normal(b0 ^ b1));
            bterm = __fmul_rn(0.001f, __fadd_rn(1.0f, noise));
        }
    }

    if (staged) {
        const GEnt* gl = &g_g[(size_t)blk * CAP];
        for (int j = threadIdx.x; j < me; j += STPB) {
            GEnt g = gl[j];
            sval[g.packed & 0x7FFFu] =
                __fmul_rn(g.w, __ldg(&actIn[g.packed >> 15]));
        }
    }
    __syncthreads();

    if (alive) {
        float acc = 0.0f;
        int d = g_deg[i];
        if (staged) {
            unsigned lo = g_lofs[i];
            #pragma unroll 8
            for (int s = 0; s < d; ++s)
                acc = __fadd_rn(acc, sval[lo + s]);          // eid-ordered chain
        } else {
            // never-taken safety net: selection by min eid over raw records
            const uint4* te = &g_tmpE[(size_t)i * MAXDEG];
            unsigned done[6] = {0, 0, 0, 0, 0, 0};
            for (int r = 0; r < d; ++r) {
                unsigned bestk = 0xFFFFFFFFu; int bs = 0;
                unsigned bsrc = 0, bw = 0;
                for (int s = 0; s < d; ++s) {
                    if (done[s >> 5] & (1u << (s & 31))) continue;
                    uint4 u4 = te[s];
                    if (u4.z < bestk) { bestk = u4.z; bs = s; bsrc = u4.x; bw = u4.y; }
                }
                done[bs >> 5] |= 1u << (bs & 31);
                acc = __fadd_rn(acc,
                    __fmul_rn(__uint_as_float(bw), __ldg(&actIn[bsrc])));
            }
        }

        float l = __fadd_rn(__fmul_rn(0.025f, acc), bterm);
        float spike = (l > 0.001378f) ? 1.0f : 0.0f;
        float na = __fsub_rn(__fadd_rn(acc, spike),
                             __fmul_rn(__fdiv_rn(acc, 0.01f), 1e-4f));
        g_spk[(size_t)t * NN + i] = spike;
        actOut[i] = na;
    }
}

// ---------------- last launch: [t][i] -> [i][t] transpose ----------------
__global__ void trans_k(float* __restrict__ out)
{
    __shared__ float tile[32][33];
    int i0 = blockIdx.x * 32, t0 = blockIdx.y * 32;
    int tr = t0 + threadIdx.y, ic = i0 + threadIdx.x;
    tile[threadIdx.y][threadIdx.x] =
        (tr < NSTEPS && ic < NN) ? g_spk[(size_t)tr * NN + ic] : 0.0f;
    __syncthreads();
    int iw = i0 + threadIdx.y, tw = t0 + threadIdx.x;
    if (iw < NN && tw < NSTEPS)
        out[(size_t)iw * NSTEPS + tw] = tile[threadIdx.x][threadIdx.y];
}

// ---------------- host ----------------
extern "C" void kernel_launch(void* const* d_in, const int* in_sizes, int n_in,
                              void* d_out, int out_size)
{
    const float* act0 = (const float*)d_in[0];
    const float* W    = (const float*)d_in[1];
    const void*  ei   = d_in[2];
    float*       out  = (float*)d_out;

    cudaFuncSetAttribute(step_k, cudaFuncAttributeMaxDynamicSharedMemorySize,
                         CAP * (int)sizeof(float));

    {
        size_t zn = (size_t)NB * NBUCK;
        prep_zero<<<(int)((zn + 255) / 256), 256>>>(ei);           // launch 0
    }
    prep_scatter <<<(EE + 255) / 256, 256>>>(ei, W);               // launch 1
    prep_csr     <<<NB, TPB>>>(act0);                              // launch 2
    prep_rankfill<<<NB, 1024>>>();                                 // launch 3

    for (int t = 0; t < NSTEPS; ++t) {                             // launch 4 = step 0
        unsigned kt0, kt1, n0, n1, f0, f1;
        tf2x32(0u, 42u, 0u, (unsigned)t, kt0, kt1);
        tf2x32(kt0, kt1, 0u, 0u, n0, n1);
        tf2x32(kt0, kt1, 0u, 1u, f0, f1);
        step_k<<<NB, STPB, CAP * sizeof(float)>>>(t, t & 1, n0, n1, f0, f1);
    }
    trans_k<<<dim3((NN + 31) / 32, (NSTEPS + 31) / 32), dim3(32, 32)>>>(out);
}